// round 1
// baseline (speedup 1.0000x reference)
#include <cuda_runtime.h>

// ---------------------------------------------------------------------------
// MultiHeadAttention_60000693125780  (GB300 / sm_103a)
// Stages:
//   1. transpose weights W[co][ci][3][3] -> Wt[tap][ci][co]   (coalesced GEMM-B)
//   2. conv q,k,v  (implicit GEMM, M=8192 pix, N=512 co, K=4608)
//   3. gather conv outputs into per-n Q/K/V matrices (512 x 256)
//   4. scores = Q K^T  (per n: 512x512x256), written to d_out attn region
//   5. softmax rows in-place
//   6. O = attn V     (per n: 512x256x512)
//   7. scatter O into conv_o input layout (4,512,8,256)
//   8. conv_o -> d_out y region
// ---------------------------------------------------------------------------

#define WSZ (4608*512)
#define NELEM 4194304          // 32*512*32*8 == 4*512*8*256

__device__ float g_Wt[4*WSZ];      // weights in [tap][ci][co] layout (q,k,v,o)
__device__ float g_y0[NELEM];      // conv(q) output (32,512,32,8)
__device__ float g_y1[NELEM];      // conv(k)
__device__ float g_y2[NELEM];      // conv(v)
__device__ float g_Qc[NELEM];      // per-n gathered Q  [n][d][h*32+r]
__device__ float g_Kc[NELEM];
__device__ float g_Vc[NELEM];
__device__ float g_On[NELEM];      // attn @ V          [n][qd][h*32+r]
__device__ float g_sa[NELEM];      // conv_o input (4,512,8,256)

// ---------------------------------------------------------------------------
// 1. Weight transpose: Wt[(t*512+ci)*512+co] = W[co*4608 + ci*9 + t]
// ---------------------------------------------------------------------------
__global__ void wtranspose(const float* __restrict__ Wq, const float* __restrict__ Wk,
                           const float* __restrict__ Wv, const float* __restrict__ Wo)
{
    __shared__ float tile[32][33];
    int wsel = blockIdx.z;
    const float* W = (wsel == 0) ? Wq : (wsel == 1) ? Wk : (wsel == 2) ? Wv : Wo;
    float* Wt = g_Wt + wsel * WSZ;
    int k0 = blockIdx.x * 32;     // k in [0,4608), k = ci*9 + t
    int co0 = blockIdx.y * 32;
#pragma unroll
    for (int j = 0; j < 4; ++j) {
        int co = co0 + threadIdx.y + j * 8;
        int kx = k0 + threadIdx.x;
        tile[threadIdx.y + j * 8][threadIdx.x] = W[co * 4608 + kx];
    }
    __syncthreads();
#pragma unroll
    for (int j = 0; j < 4; ++j) {
        int kx = k0 + threadIdx.y + j * 8;
        int co = co0 + threadIdx.x;
        int ci = kx / 9;
        int t  = kx - ci * 9;
        Wt[(t * 512 + ci) * 512 + co] = tile[threadIdx.x][threadIdx.y + j * 8];
    }
}

// ---------------------------------------------------------------------------
// Implicit-GEMM conv core. Block tile: 128 pixels x 128 cout, K-chunk 8.
// 256 threads, each computes 8x8.
// ---------------------------------------------------------------------------
__device__ __forceinline__ void conv_core(
    const float* __restrict__ x, const float* __restrict__ Wtz,
    const float* __restrict__ bias, float* __restrict__ y,
    int H, int W, int logW, int logPIX)
{
    __shared__ float As[8][128];
    __shared__ float Bs[8][128];
    const int HW = 1 << logPIX;
    int tid = threadIdx.x;
    int p0  = blockIdx.x * 128;
    int co0 = blockIdx.y * 128;
    int n     = p0 >> logPIX;          // tile never crosses an image (HW % 128 == 0)
    int pbase = p0 & (HW - 1);
    int tx = tid & 15, ty = tid >> 4;
    const float* xn = x + n * 512 * HW;

    float acc[8][8] = {};

    for (int t = 0; t < 9; ++t) {
        int dy = t / 3 - 1, dx = t % 3 - 1;
        for (int ci0 = 0; ci0 < 512; ci0 += 8) {
            // A tile: im2col gather, 128 pixels x 8 k
#pragma unroll
            for (int i = 0; i < 4; ++i) {
                int idx = i * 256 + tid;
                int kk = idx >> 7;
                int pl = idx & 127;
                int pp = pbase + pl;
                int yy = (pp >> logW) + dy;
                int xx = (pp & (W - 1)) + dx;
                float vv = 0.f;
                if ((unsigned)yy < (unsigned)H && (unsigned)xx < (unsigned)W)
                    vv = xn[(ci0 + kk) * HW + (yy << logW) + xx];
                As[kk][pl] = vv;
            }
            // B tile: pre-transposed weights, fully coalesced
#pragma unroll
            for (int i = 0; i < 4; ++i) {
                int idx = i * 256 + tid;
                int kk = idx >> 7;
                int cl = idx & 127;
                Bs[kk][cl] = Wtz[(t * 512 + ci0 + kk) * 512 + co0 + cl];
            }
            __syncthreads();
#pragma unroll
            for (int kk = 0; kk < 8; ++kk) {
                float a[8], b[8];
#pragma unroll
                for (int i = 0; i < 8; ++i) a[i] = As[kk][ty * 8 + i];
#pragma unroll
                for (int j = 0; j < 8; ++j) b[j] = Bs[kk][tx * 8 + j];
#pragma unroll
                for (int i = 0; i < 8; ++i)
#pragma unroll
                    for (int j = 0; j < 8; ++j)
                        acc[i][j] = fmaf(a[i], b[j], acc[i][j]);
            }
            __syncthreads();
        }
    }
#pragma unroll
    for (int j = 0; j < 8; ++j) {
        int co = co0 + tx * 8 + j;
        float bb = bias[co];
#pragma unroll
        for (int i = 0; i < 8; ++i) {
            int pp = pbase + ty * 8 + i;
            y[(n * 512 + co) * HW + pp] = acc[i][j] + bb;
        }
    }
}

__global__ __launch_bounds__(256, 2) void conv_qkv_kernel(
    const float* __restrict__ q, const float* __restrict__ k, const float* __restrict__ v,
    const float* __restrict__ bq, const float* __restrict__ bk, const float* __restrict__ bv)
{
    int z = blockIdx.z;
    const float* x = (z == 0) ? q : (z == 1) ? k : v;
    const float* b = (z == 0) ? bq : (z == 1) ? bk : bv;
    float* y = (z == 0) ? g_y0 : (z == 1) ? g_y1 : g_y2;
    conv_core(x, g_Wt + z * WSZ, b, y, 32, 8, 3, 8);     // H=32, W=8
}

__global__ __launch_bounds__(256, 2) void conv_o_kernel(
    const float* __restrict__ bo, float* __restrict__ out)
{
    conv_core(g_sa, g_Wt + 3 * WSZ, bo, out, 8, 256, 8, 11);  // H=8, W=256
}

// ---------------------------------------------------------------------------
// 3. Gather conv outputs into per-n matrices.
// Qc[n][d][h*32+r] = y_flat[h*524288 + n*16384 + d*32 + r]
//   which in (nimg,co,pix) layout is [h*4 + n/8][(n%8)*64 + d/8][(d%8)*32 + r]
// ---------------------------------------------------------------------------
__global__ void remap_qkv()
{
    int t = blockIdx.x * 256 + threadIdx.x;     // 3 * NELEM threads
    int which = t >> 22;
    int e = t & (NELEM - 1);
    const float* src = (which == 0) ? g_y0 : (which == 1) ? g_y1 : g_y2;
    float* dst       = (which == 0) ? g_Qc : (which == 1) ? g_Kc : g_Vc;
    int n = e >> 17;
    int d = (e >> 8) & 511;
    int h = (e >> 5) & 7;
    int r = e & 31;
    dst[e] = src[(h * 4 + (n >> 3)) * 131072 + ((n & 7) * 64 + (d >> 3)) * 256 + (d & 7) * 32 + r];
}

// ---------------------------------------------------------------------------
// 4. scores[n] = Qc[n] * Kc[n]^T   (512x512, K=256) -> d_out attn region
// ---------------------------------------------------------------------------
__global__ __launch_bounds__(256, 2) void gemm_nt_scores(float* __restrict__ attn)
{
    int nb = blockIdx.z;
    const float* A = g_Qc + nb * 131072;
    const float* B = g_Kc + nb * 131072;
    float* C = attn + (size_t)nb * 262144;
    __shared__ float As[8][128], Bs[8][128];
    int tid = threadIdx.x;
    int m0 = blockIdx.y * 128, n0 = blockIdx.x * 128;
    int tx = tid & 15, ty = tid >> 4;
    int row = tid >> 1;
    int kg = (tid & 1) * 4;
    float acc[8][8] = {};
    for (int k0 = 0; k0 < 256; k0 += 8) {
        float4 va = *(const float4*)(A + (m0 + row) * 256 + k0 + kg);
        float4 vb = *(const float4*)(B + (n0 + row) * 256 + k0 + kg);
        As[kg + 0][row] = va.x; As[kg + 1][row] = va.y; As[kg + 2][row] = va.z; As[kg + 3][row] = va.w;
        Bs[kg + 0][row] = vb.x; Bs[kg + 1][row] = vb.y; Bs[kg + 2][row] = vb.z; Bs[kg + 3][row] = vb.w;
        __syncthreads();
#pragma unroll
        for (int kk = 0; kk < 8; ++kk) {
            float a[8], b[8];
#pragma unroll
            for (int i = 0; i < 8; ++i) a[i] = As[kk][ty * 8 + i];
#pragma unroll
            for (int j = 0; j < 8; ++j) b[j] = Bs[kk][tx * 8 + j];
#pragma unroll
            for (int i = 0; i < 8; ++i)
#pragma unroll
                for (int j = 0; j < 8; ++j)
                    acc[i][j] = fmaf(a[i], b[j], acc[i][j]);
        }
        __syncthreads();
    }
#pragma unroll
    for (int i = 0; i < 8; ++i)
#pragma unroll
        for (int j = 0; j < 8; ++j)
            C[(m0 + ty * 8 + i) * 512 + n0 + tx * 8 + j] = acc[i][j];
}

// ---------------------------------------------------------------------------
// 5. softmax over 512-wide rows, in place (scale = 1/sqrt(dep) = 1)
// ---------------------------------------------------------------------------
__global__ void softmax_rows(float* __restrict__ attn)
{
    float* p = attn + (size_t)blockIdx.x * 512;
    int tid = threadIdx.x;
    float v0 = p[tid], v1 = p[tid + 256];
    float m = fmaxf(v0, v1);
#pragma unroll
    for (int o = 16; o; o >>= 1) m = fmaxf(m, __shfl_xor_sync(~0u, m, o));
    __shared__ float sm[8], ss[8];
    if ((tid & 31) == 0) sm[tid >> 5] = m;
    __syncthreads();
    if (tid < 8) {
        float mm = sm[tid];
#pragma unroll
        for (int o = 4; o; o >>= 1) mm = fmaxf(mm, __shfl_xor_sync(0xffu, mm, o));
        if (tid == 0) sm[0] = mm;
    }
    __syncthreads();
    float M = sm[0];
    float e0 = expf(v0 - M), e1 = expf(v1 - M);
    float s = e0 + e1;
#pragma unroll
    for (int o = 16; o; o >>= 1) s += __shfl_xor_sync(~0u, s, o);
    if ((tid & 31) == 0) ss[tid >> 5] = s;
    __syncthreads();
    if (tid < 8) {
        float t2 = ss[tid];
#pragma unroll
        for (int o = 4; o; o >>= 1) t2 += __shfl_xor_sync(0xffu, t2, o);
        if (tid == 0) ss[0] = t2;
    }
    __syncthreads();
    float inv = 1.f / ss[0];
    p[tid] = e0 * inv;
    p[tid + 256] = e1 * inv;
}

// ---------------------------------------------------------------------------
// 6. O[n] = attn[n] (512x512) * Vc[n] (512x256)
// ---------------------------------------------------------------------------
__global__ __launch_bounds__(256, 2) void gemm_nn_out(const float* __restrict__ attn)
{
    int nb = blockIdx.z;
    const float* A = attn + (size_t)nb * 262144;   // 512x512 row-major
    const float* B = g_Vc + nb * 131072;           // 512x256 row-major
    float* C = g_On + nb * 131072;
    __shared__ float As[8][128], Bs[8][128];
    int tid = threadIdx.x;
    int m0 = blockIdx.y * 128, n0 = blockIdx.x * 128;
    int tx = tid & 15, ty = tid >> 4;
    int rowA = tid >> 1;
    int kgA = (tid & 1) * 4;
    float acc[8][8] = {};
    for (int k0 = 0; k0 < 512; k0 += 8) {
        float4 va = *(const float4*)(A + (m0 + rowA) * 512 + k0 + kgA);
        As[kgA + 0][rowA] = va.x; As[kgA + 1][rowA] = va.y;
        As[kgA + 2][rowA] = va.z; As[kgA + 3][rowA] = va.w;
#pragma unroll
        for (int i = 0; i < 4; ++i) {
            int idx = i * 256 + tid;
            int kk = idx >> 7;
            int nl = idx & 127;
            Bs[kk][nl] = B[(k0 + kk) * 256 + n0 + nl];
        }
        __syncthreads();
#pragma unroll
        for (int kk = 0; kk < 8; ++kk) {
            float a[8], b[8];
#pragma unroll
            for (int i = 0; i < 8; ++i) a[i] = As[kk][ty * 8 + i];
#pragma unroll
            for (int j = 0; j < 8; ++j) b[j] = Bs[kk][tx * 8 + j];
#pragma unroll
            for (int i = 0; i < 8; ++i)
#pragma unroll
                for (int j = 0; j < 8; ++j)
                    acc[i][j] = fmaf(a[i], b[j], acc[i][j]);
        }
        __syncthreads();
    }
#pragma unroll
    for (int i = 0; i < 8; ++i)
#pragma unroll
        for (int j = 0; j < 8; ++j)
            C[(m0 + ty * 8 + i) * 256 + n0 + tx * 8 + j] = acc[i][j];
}

// ---------------------------------------------------------------------------
// 7. scatter O into conv_o input (B=4, D=512, S=8, RH=256), write-coalesced
// sa[b,d2,s,r2*8+h2] = On[n=b*8+s][qd=r2*16+h2*2+(d2>>8)][h=d2&7, r=(d2&255)>>3]
// ---------------------------------------------------------------------------
__global__ void remap_sa()
{
    int e = blockIdx.x * 256 + threadIdx.x;   // NELEM threads
    int b  = e >> 20;
    int d2 = (e >> 11) & 511;
    int s  = (e >> 8) & 7;
    int rh = e & 255;
    int r2 = rh >> 3, h2 = rh & 7;
    int n  = b * 8 + s;
    int qd = r2 * 16 + h2 * 2 + (d2 >> 8);
    int rr = (d2 & 255) >> 3;
    int hh = d2 & 7;
    g_sa[e] = g_On[n * 131072 + qd * 256 + hh * 32 + rr];
}

// ---------------------------------------------------------------------------
extern "C" void kernel_launch(void* const* d_in, const int* in_sizes, int n_in,
                              void* d_out, int out_size)
{
    const float* q  = (const float*)d_in[0];
    const float* k  = (const float*)d_in[1];
    const float* v  = (const float*)d_in[2];
    const float* Wq = (const float*)d_in[3];
    const float* bq = (const float*)d_in[4];
    const float* Wk = (const float*)d_in[5];
    const float* bk = (const float*)d_in[6];
    const float* Wv = (const float*)d_in[7];
    const float* bv = (const float*)d_in[8];
    const float* Wo = (const float*)d_in[9];
    const float* bo = (const float*)d_in[10];

    float* y_out    = (float*)d_out;            // (4,512,8,32,8) = 4194304
    float* attn_out = y_out + NELEM;            // (1,32,512,512) = 8388608

    wtranspose<<<dim3(144, 16, 4), dim3(32, 8)>>>(Wq, Wk, Wv, Wo);
    conv_qkv_kernel<<<dim3(64, 4, 3), 256>>>(q, k, v, bq, bk, bv);
    remap_qkv<<<3 * NELEM / 256, 256>>>();
    gemm_nt_scores<<<dim3(4, 4, 32), 256>>>(attn_out);
    softmax_rows<<<32 * 512, 256>>>(attn_out);
    gemm_nn_out<<<dim3(2, 4, 32), 256>>>(attn_out);
    remap_sa<<<NELEM / 256, 256>>>();
    conv_o_kernel<<<dim3(64, 4, 1), 256>>>(bo, y_out);
}

// round 3
// speedup vs baseline: 2.3192x; 2.3192x over previous
#include <cuda_runtime.h>
#include <cuda_bf16.h>
#include <cstdint>

#define NELEM 4194304          // 32*512*32*8 == 4*512*8*256
#define WSZ   2359296          // 512*4608 weight elements per conv

// ---------------------------------------------------------------------------
// device scratch
// ---------------------------------------------------------------------------
__device__ __nv_bfloat16 g_Bh[4*WSZ];   // weights hi  [conv][co][t*512+ci]
__device__ __nv_bfloat16 g_Bl[4*WSZ];   // weights lo
__device__ __nv_bfloat16 g_xh[3*NELEM]; // qkv inputs hi, pixel-major [z][n][p][ci]
__device__ __nv_bfloat16 g_xl[3*NELEM];
__device__ __nv_bfloat16 g_sah[NELEM];  // conv_o input hi [b][p][ci]
__device__ __nv_bfloat16 g_sal[NELEM];
__device__ float g_y0[NELEM];           // conv(q) out (32,512,32,8)
__device__ float g_y1[NELEM];
__device__ float g_y2[NELEM];
__device__ float g_Qc[NELEM];           // per-n gathered Q  [n][d][h*32+r]
__device__ float g_Kc[NELEM];
__device__ float g_Vc[NELEM];
__device__ float g_On[NELEM];           // attn @ V  [n][qd][h*32+r]

// ---------------------------------------------------------------------------
// helpers
// ---------------------------------------------------------------------------
__device__ __forceinline__ uint32_t smem_u32(const void* p) {
    uint32_t a;
    asm("{ .reg .u64 t; cvta.to.shared.u64 t, %1; cvt.u32.u64 %0, t; }" : "=r"(a) : "l"(p));
    return a;
}
#define SWZ(o) ((o) ^ (((o) >> 3) & 0x70))
#define STS128V(addr, v) \
    asm volatile("st.shared.v4.b32 [%0], {%1,%2,%3,%4};" \
        :: "r"(addr), "r"((v).x), "r"((v).y), "r"((v).z), "r"((v).w) : "memory")
#define LDM4(r, addr) \
    asm volatile("ldmatrix.sync.aligned.m8n8.x4.shared.b16 {%0,%1,%2,%3}, [%4];" \
        : "=r"((r)[0]), "=r"((r)[1]), "=r"((r)[2]), "=r"((r)[3]) : "r"(addr))
#define MMA_BF16(d, a, b0, b1) \
    asm volatile("mma.sync.aligned.m16n8k16.row.col.f32.bf16.bf16.f32 " \
        "{%0,%1,%2,%3}, {%4,%5,%6,%7}, {%8,%9}, {%0,%1,%2,%3};" \
        : "+f"((d)[0]), "+f"((d)[1]), "+f"((d)[2]), "+f"((d)[3]) \
        : "r"((a)[0]), "r"((a)[1]), "r"((a)[2]), "r"((a)[3]), "r"(b0), "r"(b1))

// SMEM layout (dynamic): Ah 0..16K, Al 16K, Bh 32K, Bl 48K; epilogue reuses as
// 128x130 fp32 tile. Total 66560 bytes.
#define OFF_AH 0u
#define OFF_AL 16384u
#define OFF_BH 32768u
#define OFF_BL 49152u
#define SMEM_BYTES 66560

// ---------------------------------------------------------------------------
// pre-pass: weights -> bf16 hi/lo in [co][t*512+ci] layout
// ---------------------------------------------------------------------------
__global__ void prep_w(const float* __restrict__ Wq, const float* __restrict__ Wk,
                       const float* __restrict__ Wv, const float* __restrict__ Wo)
{
    int g = blockIdx.x * 256 + threadIdx.x;            // 4*WSZ threads
    int conv = g / WSZ;
    int j = g - conv * WSZ;
    const float* W = (conv == 0) ? Wq : (conv == 1) ? Wk : (conv == 2) ? Wv : Wo;
    float v = W[j];
    int co  = j / 4608;
    int rem = j - co * 4608;
    int ci  = rem / 9;
    int t   = rem - ci * 9;
    __nv_bfloat16 h = __float2bfloat16(v);
    __nv_bfloat16 l = __float2bfloat16(v - __bfloat162float(h));
    size_t o = (size_t)conv * WSZ + (size_t)co * 4608 + t * 512 + ci;
    g_Bh[o] = h;
    g_Bl[o] = l;
}

// ---------------------------------------------------------------------------
// pre-pass: q/k/v (32 imgs, 512 ch, 256 pix) -> pixel-major bf16 hi/lo
// ---------------------------------------------------------------------------
__global__ void prep_x(const float* __restrict__ q, const float* __restrict__ k,
                       const float* __restrict__ v)
{
    __shared__ float tile[32][33];
    int z = blockIdx.z >> 5;
    int n = blockIdx.z & 31;
    const float* src = (z == 0) ? q : (z == 1) ? k : v;
    const float* xin = src + (size_t)n * 512 * 256;
    __nv_bfloat16* oh = g_xh + (size_t)z * NELEM + (size_t)n * 256 * 512;
    __nv_bfloat16* ol = g_xl + (size_t)z * NELEM + (size_t)n * 256 * 512;
    int p0 = blockIdx.x * 32;
    int c0 = blockIdx.y * 32;
    int tx = threadIdx.x, ty = threadIdx.y;
#pragma unroll
    for (int j = 0; j < 4; ++j)
        tile[ty + 8 * j][tx] = xin[(size_t)(c0 + ty + 8 * j) * 256 + p0 + tx];
    __syncthreads();
#pragma unroll
    for (int j = 0; j < 4; ++j) {
        float val = tile[tx][ty + 8 * j];
        __nv_bfloat16 h = __float2bfloat16(val);
        size_t o = (size_t)(p0 + ty + 8 * j) * 512 + c0 + tx;
        oh[o] = h;
        ol[o] = __float2bfloat16(val - __bfloat162float(h));
    }
}

// ---------------------------------------------------------------------------
// mma.sync implicit-GEMM conv core. CTA tile: M=128 pixels x N=128 cout.
// 8 warps (2 x 4), warp tile 64x32. K streamed in 64-chunks (tap-major).
// fp32 emulation: D += Ah*Bh + Ah*Bl + Al*Bh  (bf16 hi/lo split).
// ---------------------------------------------------------------------------
__device__ __forceinline__ void conv_mma_core(
    const __nv_bfloat16* __restrict__ xh, const __nv_bfloat16* __restrict__ xl,
    const __nv_bfloat16* __restrict__ bh, const __nv_bfloat16* __restrict__ bl,
    const float* __restrict__ bias, float* __restrict__ y,
    int H, int W, int logW, int logPIX)
{
    extern __shared__ char smem[];
    uint32_t sb = smem_u32(smem);
    int tid = threadIdx.x, wid = tid >> 5, lane = tid & 31;
    const int HW = 1 << logPIX;
    int p0    = blockIdx.x * 128;
    int nimg  = p0 >> logPIX;              // 128 | HW -> tile never crosses image
    int pbase = p0 & (HW - 1);
    int co0   = blockIdx.y * 128;

    int wm = wid & 1, wn = wid >> 1;       // warp coords: 2 x 4

    // ---- loader geometry
    int ar = tid >> 1, aseg = tid & 1;     // A: pixel row, 64B half
    int ap = pbase + ar;
    int ayr = ap >> logW, axr = ap & (W - 1);
    uint32_t arawb = (uint32_t)(ar * 128 + aseg * 64);
    int br = tid >> 1, bseg = tid & 1;     // B: cout row, 64B half
    uint32_t brawb = (uint32_t)(br * 128 + bseg * 64);
    const __nv_bfloat16* brow_h = bh + (size_t)(co0 + br) * 4608 + bseg * 32;
    const __nv_bfloat16* brow_l = bl + (size_t)(co0 + br) * 4608 + bseg * 32;

    // ---- ldmatrix lane geometry
    uint32_t a_rowb = (uint32_t)((wm * 64 + (lane & 15)) * 128) + ((lane & 16) ? 16u : 0u);
    uint32_t b_rowb = (uint32_t)((wn * 32 + (lane & 7) + ((lane & 16) ? 8 : 0)) * 128)
                    + ((lane & 8) ? 16u : 0u);

    float acc[16][4];
#pragma unroll
    for (int i = 0; i < 16; ++i)
#pragma unroll
        for (int j = 0; j < 4; ++j) acc[i][j] = 0.f;

    for (int t = 0; t < 9; ++t) {
        int dy = t / 3 - 1, dx = t % 3 - 1;
        int yy = ayr + dy, xx = axr + dx;
        bool ok = ((unsigned)yy < (unsigned)H) && ((unsigned)xx < (unsigned)W);
        int pps = ok ? ((yy << logW) + xx) : 0;
        const uint4* arh = (const uint4*)(xh + ((size_t)nimg * HW + pps) * 512 + aseg * 32);
        const uint4* arl = (const uint4*)(xl + ((size_t)nimg * HW + pps) * 512 + aseg * 32);
        for (int ci0 = 0; ci0 < 512; ci0 += 64) {
            // ---- fill SMEM (A 128x64 hi/lo, B 128x64 hi/lo)
            {
                const uint4* sah_ = arh + (ci0 >> 3);
                const uint4* sal_ = arl + (ci0 >> 3);
                const uint4* sbh_ = (const uint4*)(brow_h + t * 512 + ci0);
                const uint4* sbl_ = (const uint4*)(brow_l + t * 512 + ci0);
                uint4 z4 = make_uint4(0, 0, 0, 0);
#pragma unroll
                for (int j = 0; j < 4; ++j) {
                    uint4 vh = ok ? sah_[j] : z4;
                    uint4 vl = ok ? sal_[j] : z4;
                    uint32_t swa = SWZ(arawb + j * 16);
                    STS128V(sb + OFF_AH + swa, vh);
                    STS128V(sb + OFF_AL + swa, vl);
                    uint4 wh = sbh_[j];
                    uint4 wl = sbl_[j];
                    uint32_t swb = SWZ(brawb + j * 16);
                    STS128V(sb + OFF_BH + swb, wh);
                    STS128V(sb + OFF_BL + swb, wl);
                }
            }
            __syncthreads();
            // ---- compute 4 K16 steps
#pragma unroll
            for (int s = 0; s < 4; ++s) {
                uint32_t ah[4][4], bb[2][4], blf[2][4];
#pragma unroll
                for (int i = 0; i < 4; ++i)
                    LDM4(ah[i], sb + OFF_AH + SWZ(a_rowb + i * 2048 + s * 32));
#pragma unroll
                for (int j = 0; j < 2; ++j)
                    LDM4(bb[j], sb + OFF_BH + SWZ(b_rowb + j * 2048 + s * 32));
                // Ah * Bh
#pragma unroll
                for (int i = 0; i < 4; ++i)
#pragma unroll
                    for (int jj = 0; jj < 4; ++jj)
                        MMA_BF16(acc[i * 4 + jj], ah[i],
                                 bb[jj >> 1][(jj & 1) * 2], bb[jj >> 1][(jj & 1) * 2 + 1]);
                // Ah * Bl
#pragma unroll
                for (int j = 0; j < 2; ++j)
                    LDM4(blf[j], sb + OFF_BL + SWZ(b_rowb + j * 2048 + s * 32));
#pragma unroll
                for (int i = 0; i < 4; ++i)
#pragma unroll
                    for (int jj = 0; jj < 4; ++jj)
                        MMA_BF16(acc[i * 4 + jj], ah[i],
                                 blf[jj >> 1][(jj & 1) * 2], blf[jj >> 1][(jj & 1) * 2 + 1]);
                // Al * Bh  (Al overwrites Ah regs)
#pragma unroll
                for (int i = 0; i < 4; ++i)
                    LDM4(ah[i], sb + OFF_AL + SWZ(a_rowb + i * 2048 + s * 32));
#pragma unroll
                for (int i = 0; i < 4; ++i)
#pragma unroll
                    for (int jj = 0; jj < 4; ++jj)
                        MMA_BF16(acc[i * 4 + jj], ah[i],
                                 bb[jj >> 1][(jj & 1) * 2], bb[jj >> 1][(jj & 1) * 2 + 1]);
            }
            __syncthreads();
        }
    }

    // ---- epilogue: stage via SMEM (128 x 130 fp32) for coalesced stores
    float* sf = (float*)smem;
#pragma unroll
    for (int i = 0; i < 4; ++i) {
        int row = wm * 64 + i * 16 + (lane >> 2);
#pragma unroll
        for (int jj = 0; jj < 4; ++jj) {
            int col = wn * 32 + jj * 8 + (lane & 3) * 2;
            float* d = acc[i * 4 + jj];
            *(float2*)&sf[row * 130 + col]       = make_float2(d[0], d[1]);
            *(float2*)&sf[(row + 8) * 130 + col] = make_float2(d[2], d[3]);
        }
    }
    __syncthreads();
    {
        int pl = tid & 127, co2 = tid >> 7;
        float* yb = y + (size_t)nimg * 512 * HW + pbase + pl;
#pragma unroll 4
        for (int c = 0; c < 64; ++c) {
            int cl = c * 2 + co2;
            yb[(size_t)(co0 + cl) * HW] = sf[pl * 130 + cl] + bias[co0 + cl];
        }
    }
}

__global__ __launch_bounds__(256, 2) void conv_qkv_mma(
    const float* __restrict__ bq, const float* __restrict__ bk, const float* __restrict__ bv)
{
    int z = blockIdx.z;
    const float* bias = (z == 0) ? bq : (z == 1) ? bk : bv;
    float* y = (z == 0) ? g_y0 : (z == 1) ? g_y1 : g_y2;
    conv_mma_core(g_xh + (size_t)z * NELEM, g_xl + (size_t)z * NELEM,
                  g_Bh + (size_t)z * WSZ, g_Bl + (size_t)z * WSZ,
                  bias, y, 32, 8, 3, 8);
}

__global__ __launch_bounds__(256, 2) void conv_o_mma(const float* __restrict__ bo,
                                                     float* __restrict__ out)
{
    conv_mma_core(g_sah, g_sal, g_Bh + 3ull * WSZ, g_Bl + 3ull * WSZ,
                  bo, out, 8, 256, 8, 11);
}

// ---------------------------------------------------------------------------
// gather conv outputs into per-n Q/K/V matrices
// ---------------------------------------------------------------------------
__global__ void remap_qkv()
{
    int t = blockIdx.x * 256 + threadIdx.x;     // 3 * NELEM threads
    int which = t >> 22;
    int e = t & (NELEM - 1);
    const float* src = (which == 0) ? g_y0 : (which == 1) ? g_y1 : g_y2;
    float* dst       = (which == 0) ? g_Qc : (which == 1) ? g_Kc : g_Vc;
    int n = e >> 17;
    int d = (e >> 8) & 511;
    int h = (e >> 5) & 7;
    int r = e & 31;
    dst[e] = src[(h * 4 + (n >> 3)) * 131072 + ((n & 7) * 64 + (d >> 3)) * 256 + (d & 7) * 32 + r];
}

// ---------------------------------------------------------------------------
// scores[n] = Qc[n] * Kc[n]^T  (512x512, K=256) -> d_out attn region
// ---------------------------------------------------------------------------
__global__ __launch_bounds__(256, 2) void gemm_nt_scores(float* __restrict__ attn)
{
    int nb = blockIdx.z;
    const float* A = g_Qc + nb * 131072;
    const float* B = g_Kc + nb * 131072;
    float* C = attn + (size_t)nb * 262144;
    __shared__ float As[8][128], Bs[8][128];
    int tid = threadIdx.x;
    int m0 = blockIdx.y * 128, n0 = blockIdx.x * 128;
    int tx = tid & 15, ty = tid >> 4;
    int row = tid >> 1;
    int kg = (tid & 1) * 4;
    float acc[8][8] = {};
    for (int k0 = 0; k0 < 256; k0 += 8) {
        float4 va = *(const float4*)(A + (m0 + row) * 256 + k0 + kg);
        float4 vb = *(const float4*)(B + (n0 + row) * 256 + k0 + kg);
        As[kg + 0][row] = va.x; As[kg + 1][row] = va.y; As[kg + 2][row] = va.z; As[kg + 3][row] = va.w;
        Bs[kg + 0][row] = vb.x; Bs[kg + 1][row] = vb.y; Bs[kg + 2][row] = vb.z; Bs[kg + 3][row] = vb.w;
        __syncthreads();
#pragma unroll
        for (int kk = 0; kk < 8; ++kk) {
            float a[8], b[8];
#pragma unroll
            for (int i = 0; i < 8; ++i) a[i] = As[kk][ty * 8 + i];
#pragma unroll
            for (int j = 0; j < 8; ++j) b[j] = Bs[kk][tx * 8 + j];
#pragma unroll
            for (int i = 0; i < 8; ++i)
#pragma unroll
                for (int j = 0; j < 8; ++j)
                    acc[i][j] = fmaf(a[i], b[j], acc[i][j]);
        }
        __syncthreads();
    }
#pragma unroll
    for (int i = 0; i < 8; ++i)
#pragma unroll
        for (int j = 0; j < 8; ++j)
            C[(m0 + ty * 8 + i) * 512 + n0 + tx * 8 + j] = acc[i][j];
}

// ---------------------------------------------------------------------------
// softmax over 512-wide rows, in place
// ---------------------------------------------------------------------------
__global__ void softmax_rows(float* __restrict__ attn)
{
    float* p = attn + (size_t)blockIdx.x * 512;
    int tid = threadIdx.x;
    float v0 = p[tid], v1 = p[tid + 256];
    float m = fmaxf(v0, v1);
#pragma unroll
    for (int o = 16; o; o >>= 1) m = fmaxf(m, __shfl_xor_sync(~0u, m, o));
    __shared__ float sm[8], ss[8];
    if ((tid & 31) == 0) sm[tid >> 5] = m;
    __syncthreads();
    if (tid < 8) {
        float mm = sm[tid];
#pragma unroll
        for (int o = 4; o; o >>= 1) mm = fmaxf(mm, __shfl_xor_sync(0xffu, mm, o));
        if (tid == 0) sm[0] = mm;
    }
    __syncthreads();
    float M = sm[0];
    float e0 = expf(v0 - M), e1 = expf(v1 - M);
    float s = e0 + e1;
#pragma unroll
    for (int o = 16; o; o >>= 1) s += __shfl_xor_sync(~0u, s, o);
    if ((tid & 31) == 0) ss[tid >> 5] = s;
    __syncthreads();
    if (tid < 8) {
        float t2 = ss[tid];
#pragma unroll
        for (int o = 4; o; o >>= 1) t2 += __shfl_xor_sync(0xffu, t2, o);
        if (tid == 0) ss[0] = t2;
    }
    __syncthreads();
    float inv = 1.f / ss[0];
    p[tid] = e0 * inv;
    p[tid + 256] = e1 * inv;
}

// ---------------------------------------------------------------------------
// O[n] = attn[n] (512x512) * Vc[n] (512x256)
// ---------------------------------------------------------------------------
__global__ __launch_bounds__(256, 2) void gemm_nn_out(const float* __restrict__ attn)
{
    int nb = blockIdx.z;
    const float* A = attn + (size_t)nb * 262144;
    const float* B = g_Vc + nb * 131072;
    float* C = g_On + nb * 131072;
    __shared__ float As[8][128], Bs[8][128];
    int tid = threadIdx.x;
    int m0 = blockIdx.y * 128, n0 = blockIdx.x * 128;
    int tx = tid & 15, ty = tid >> 4;
    int rowA = tid >> 1;
    int kgA = (tid & 1) * 4;
    float acc[8][8] = {};
    for (int k0 = 0; k0 < 512; k0 += 8) {
        float4 va = *(const float4*)(A + (m0 + rowA) * 512 + k0 + kgA);
        As[kgA + 0][rowA] = va.x; As[kgA + 1][rowA] = va.y;
        As[kgA + 2][rowA] = va.z; As[kgA + 3][rowA] = va.w;
#pragma unroll
        for (int i = 0; i < 4; ++i) {
            int idx = i * 256 + tid;
            int kk = idx >> 7;
            int nl = idx & 127;
            Bs[kk][nl] = B[(k0 + kk) * 256 + n0 + nl];
        }
        __syncthreads();
#pragma unroll
        for (int kk = 0; kk < 8; ++kk) {
            float a[8], b[8];
#pragma unroll
            for (int i = 0; i < 8; ++i) a[i] = As[kk][ty * 8 + i];
#pragma unroll
            for (int j = 0; j < 8; ++j) b[j] = Bs[kk][tx * 8 + j];
#pragma unroll
            for (int i = 0; i < 8; ++i)
#pragma unroll
                for (int j = 0; j < 8; ++j)
                    acc[i][j] = fmaf(a[i], b[j], acc[i][j]);
        }
        __syncthreads();
    }
#pragma unroll
    for (int i = 0; i < 8; ++i)
#pragma unroll
        for (int j = 0; j < 8; ++j)
            C[(m0 + ty * 8 + i) * 256 + n0 + tx * 8 + j] = acc[i][j];
}

// ---------------------------------------------------------------------------
// scatter O into conv_o input, pixel-major bf16 hi/lo [b][p][ci]
// ---------------------------------------------------------------------------
__global__ void remap_sa_bf16()
{
    int e = blockIdx.x * 256 + threadIdx.x;   // NELEM threads; [b][p=s*256+rh][d2]
    int b  = e >> 20;
    int p  = (e >> 9) & 2047;
    int d2 = e & 511;
    int s  = p >> 8;
    int rh = p & 255;
    int r2 = rh >> 3, h2 = rh & 7;
    int n  = b * 8 + s;
    int qd = r2 * 16 + h2 * 2 + (d2 >> 8);
    int rr = (d2 & 255) >> 3;
    int hh = d2 & 7;
    float v = g_On[n * 131072 + qd * 256 + hh * 32 + rr];
    __nv_bfloat16 h = __float2bfloat16(v);
    g_sah[e] = h;
    g_sal[e] = __float2bfloat16(v - __bfloat162float(h));
}

// ---------------------------------------------------------------------------
extern "C" void kernel_launch(void* const* d_in, const int* in_sizes, int n_in,
                              void* d_out, int out_size)
{
    const float* q  = (const float*)d_in[0];
    const float* k  = (const float*)d_in[1];
    const float* v  = (const float*)d_in[2];
    const float* Wq = (const float*)d_in[3];
    const float* bq = (const float*)d_in[4];
    const float* Wk = (const float*)d_in[5];
    const float* bk = (const float*)d_in[6];
    const float* Wv = (const float*)d_in[7];
    const float* bv = (const float*)d_in[8];
    const float* Wo = (const float*)d_in[9];
    const float* bo = (const float*)d_in[10];

    float* y_out    = (float*)d_out;            // (4,512,8,32,8) = 4194304
    float* attn_out = y_out + NELEM;            // (1,32,512,512) = 8388608

    cudaFuncSetAttribute(conv_qkv_mma, cudaFuncAttributeMaxDynamicSharedMemorySize, SMEM_BYTES);
    cudaFuncSetAttribute(conv_o_mma,   cudaFuncAttributeMaxDynamicSharedMemorySize, SMEM_BYTES);

    prep_w<<<4 * WSZ / 256, 256>>>(Wq, Wk, Wv, Wo);
    prep_x<<<dim3(8, 16, 96), dim3(32, 8)>>>(q, k, v);
    conv_qkv_mma<<<dim3(64, 4, 3), 256, SMEM_BYTES>>>(bq, bk, bv);
    remap_qkv<<<3 * NELEM / 256, 256>>>();
    gemm_nt_scores<<<dim3(4, 4, 32), 256>>>(attn_out);
    softmax_rows<<<32 * 512, 256>>>(attn_out);
    gemm_nn_out<<<dim3(2, 4, 32), 256>>>(attn_out);
    remap_sa_bf16<<<NELEM / 256, 256>>>();
    conv_o_mma<<<dim3(64, 4, 1), 256, SMEM_BYTES>>>(bo, y_out);
}

// round 4
// speedup vs baseline: 2.3910x; 1.0310x over previous
#include <cuda_runtime.h>
#include <cuda_bf16.h>
#include <cstdint>

#define NELEM 4194304          // 32*512*32*8 == 4*512*8*256
#define WSZ   2359296          // 512*4608 weight elements per conv

// ---------------------------------------------------------------------------
// device scratch
// ---------------------------------------------------------------------------
__device__ __nv_bfloat16 g_Bh[4*WSZ];   // weights hi  [conv][co][t*512+ci]
__device__ __nv_bfloat16 g_Bl[4*WSZ];   // weights lo
__device__ __nv_bfloat16 g_xh[3*NELEM]; // qkv inputs hi, pixel-major [z][n][p][ci]
__device__ __nv_bfloat16 g_xl[3*NELEM];
__device__ __nv_bfloat16 g_sah[NELEM];  // conv_o input hi [b][p][ci]
__device__ __nv_bfloat16 g_sal[NELEM];
__device__ float g_y0[NELEM];           // conv(q) out (32,512,32,8)
__device__ float g_y1[NELEM];
__device__ float g_y2[NELEM];
__device__ __nv_bfloat16 g_Qh[NELEM], g_Ql[NELEM];   // [n][d][c], c=h*32+r
__device__ __nv_bfloat16 g_Kh[NELEM], g_Kl[NELEM];
__device__ __nv_bfloat16 g_Vth[NELEM], g_Vtl[NELEM]; // transposed: [n][c][dk]
__device__ __nv_bfloat16 g_ath[2*NELEM], g_atl[2*NELEM]; // attn hi/lo
__device__ float g_On[NELEM];           // attn @ V  [n][qd][c]

// ---------------------------------------------------------------------------
// helpers
// ---------------------------------------------------------------------------
__device__ __forceinline__ uint32_t smem_u32(const void* p) {
    uint32_t a;
    asm("{ .reg .u64 t; cvta.to.shared.u64 t, %1; cvt.u32.u64 %0, t; }" : "=r"(a) : "l"(p));
    return a;
}
#define SWZ(o) ((o) ^ (((o) >> 3) & 0x70))
#define CPA(dst, src, sz) \
    asm volatile("cp.async.cg.shared.global [%0], [%1], 16, %2;" \
        :: "r"(dst), "l"(src), "r"(sz) : "memory")
#define CPA_COMMIT() asm volatile("cp.async.commit_group;" ::: "memory")
#define CPA_WAIT1()  asm volatile("cp.async.wait_group 1;" ::: "memory")
#define CPA_WAIT0()  asm volatile("cp.async.wait_group 0;" ::: "memory")
#define LDM4(r, addr) \
    asm volatile("ldmatrix.sync.aligned.m8n8.x4.shared.b16 {%0,%1,%2,%3}, [%4];" \
        : "=r"((r)[0]), "=r"((r)[1]), "=r"((r)[2]), "=r"((r)[3]) : "r"(addr))
#define MMA_BF16(d, a, b0, b1) \
    asm volatile("mma.sync.aligned.m16n8k16.row.col.f32.bf16.bf16.f32 " \
        "{%0,%1,%2,%3}, {%4,%5,%6,%7}, {%8,%9}, {%0,%1,%2,%3};" \
        : "+f"((d)[0]), "+f"((d)[1]), "+f"((d)[2]), "+f"((d)[3]) \
        : "r"((a)[0]), "r"((a)[1]), "r"((a)[2]), "r"((a)[3]), "r"(b0), "r"(b1))

// per-stage layout: Ah 0, Al 16K, Bh 32K, Bl 48K; stage stride 64K; 3 stages
#define STAGE_BYTES 65536u
#define SMEM_BYTES  196608

// compute one K64 chunk: D += Ah*Bh + Ah*Bl + Al*Bh
__device__ __forceinline__ void mma_compute64(uint32_t bs, uint32_t a_rowb,
                                              uint32_t b_rowb, float (&acc)[16][4])
{
#pragma unroll
    for (int s = 0; s < 4; ++s) {
        uint32_t ah[4][4], bb[2][4], blf[2][4];
#pragma unroll
        for (int i = 0; i < 4; ++i)
            LDM4(ah[i], bs + SWZ(a_rowb + i * 2048 + s * 32));
#pragma unroll
        for (int j = 0; j < 2; ++j)
            LDM4(bb[j], bs + 32768u + SWZ(b_rowb + j * 2048 + s * 32));
#pragma unroll
        for (int i = 0; i < 4; ++i)
#pragma unroll
            for (int jj = 0; jj < 4; ++jj)
                MMA_BF16(acc[i * 4 + jj], ah[i],
                         bb[jj >> 1][(jj & 1) * 2], bb[jj >> 1][(jj & 1) * 2 + 1]);
#pragma unroll
        for (int j = 0; j < 2; ++j)
            LDM4(blf[j], bs + 49152u + SWZ(b_rowb + j * 2048 + s * 32));
#pragma unroll
        for (int i = 0; i < 4; ++i)
#pragma unroll
            for (int jj = 0; jj < 4; ++jj)
                MMA_BF16(acc[i * 4 + jj], ah[i],
                         blf[jj >> 1][(jj & 1) * 2], blf[jj >> 1][(jj & 1) * 2 + 1]);
#pragma unroll
        for (int i = 0; i < 4; ++i)
            LDM4(ah[i], bs + 16384u + SWZ(a_rowb + i * 2048 + s * 32));
#pragma unroll
        for (int i = 0; i < 4; ++i)
#pragma unroll
            for (int jj = 0; jj < 4; ++jj)
                MMA_BF16(acc[i * 4 + jj], ah[i],
                         bb[jj >> 1][(jj & 1) * 2], bb[jj >> 1][(jj & 1) * 2 + 1]);
    }
}

// ---------------------------------------------------------------------------
// pre-pass: weights -> bf16 hi/lo in [co][t*512+ci] layout
// ---------------------------------------------------------------------------
__global__ void prep_w(const float* __restrict__ Wq, const float* __restrict__ Wk,
                       const float* __restrict__ Wv, const float* __restrict__ Wo)
{
    int g = blockIdx.x * 256 + threadIdx.x;
    int conv = g / WSZ;
    int j = g - conv * WSZ;
    const float* W = (conv == 0) ? Wq : (conv == 1) ? Wk : (conv == 2) ? Wv : Wo;
    float v = W[j];
    int co  = j / 4608;
    int rem = j - co * 4608;
    int ci  = rem / 9;
    int t   = rem - ci * 9;
    __nv_bfloat16 h = __float2bfloat16(v);
    __nv_bfloat16 l = __float2bfloat16(v - __bfloat162float(h));
    size_t o = (size_t)conv * WSZ + (size_t)co * 4608 + t * 512 + ci;
    g_Bh[o] = h;
    g_Bl[o] = l;
}

// ---------------------------------------------------------------------------
// pre-pass: q/k/v (32 imgs, 512 ch, 256 pix) -> pixel-major bf16 hi/lo
// ---------------------------------------------------------------------------
__global__ void prep_x(const float* __restrict__ q, const float* __restrict__ k,
                       const float* __restrict__ v)
{
    __shared__ float tile[32][33];
    int z = blockIdx.z >> 5;
    int n = blockIdx.z & 31;
    const float* src = (z == 0) ? q : (z == 1) ? k : v;
    const float* xin = src + (size_t)n * 512 * 256;
    __nv_bfloat16* oh = g_xh + (size_t)z * NELEM + (size_t)n * 256 * 512;
    __nv_bfloat16* ol = g_xl + (size_t)z * NELEM + (size_t)n * 256 * 512;
    int p0 = blockIdx.x * 32;
    int c0 = blockIdx.y * 32;
    int tx = threadIdx.x, ty = threadIdx.y;
#pragma unroll
    for (int j = 0; j < 4; ++j)
        tile[ty + 8 * j][tx] = xin[(size_t)(c0 + ty + 8 * j) * 256 + p0 + tx];
    __syncthreads();
#pragma unroll
    for (int j = 0; j < 4; ++j) {
        float val = tile[tx][ty + 8 * j];
        __nv_bfloat16 h = __float2bfloat16(val);
        size_t o = (size_t)(p0 + ty + 8 * j) * 512 + c0 + tx;
        oh[o] = h;
        ol[o] = __float2bfloat16(val - __bfloat162float(h));
    }
}

// ---------------------------------------------------------------------------
// 3-stage cp.async pipelined implicit-GEMM conv. M=128 pix x N=128 co.
// ---------------------------------------------------------------------------
__device__ __forceinline__ void conv_mma_pipe(
    const __nv_bfloat16* __restrict__ xh, const __nv_bfloat16* __restrict__ xl,
    const __nv_bfloat16* __restrict__ bh, const __nv_bfloat16* __restrict__ bl,
    const float* __restrict__ bias, float* __restrict__ y,
    int H, int W, int logW, int logPIX)
{
    extern __shared__ char smem[];
    uint32_t sb = smem_u32(smem);
    int tid = threadIdx.x, wid = tid >> 5, lane = tid & 31;
    const int HW = 1 << logPIX;
    int p0    = blockIdx.x * 128;
    int nimg  = p0 >> logPIX;
    int pbase = p0 & (HW - 1);
    int co0   = blockIdx.y * 128;
    int wm = wid & 1, wn = wid >> 1;

    int ar = tid >> 1, aseg = tid & 1;
    int ap = pbase + ar;
    int ayr = ap >> logW, axr = ap & (W - 1);
    uint32_t rawb = (uint32_t)(ar * 128 + aseg * 64);
    const __nv_bfloat16* arow_h = xh + (size_t)nimg * HW * 512 + aseg * 32;
    const __nv_bfloat16* arow_l = xl + (size_t)nimg * HW * 512 + aseg * 32;
    const __nv_bfloat16* brow_h = bh + (size_t)(co0 + ar) * 4608 + aseg * 32;
    const __nv_bfloat16* brow_l = bl + (size_t)(co0 + ar) * 4608 + aseg * 32;

    uint32_t a_rowb = (uint32_t)((wm * 64 + (lane & 15)) * 128) + ((lane & 16) ? 16u : 0u);
    uint32_t b_rowb = (uint32_t)((wn * 32 + (lane & 7) + ((lane & 16) ? 8 : 0)) * 128)
                    + ((lane & 8) ? 16u : 0u);

    float acc[16][4];
#pragma unroll
    for (int i = 0; i < 16; ++i)
#pragma unroll
        for (int j = 0; j < 4; ++j) acc[i][j] = 0.f;

    auto prefetch = [&](int itn, int stg) {
        int t = itn >> 3, ci0 = (itn & 7) << 6;
        int q3 = (t * 11) >> 5;                 // t/3 for t in [0,9)
        int dy = q3 - 1, dx = t - q3 * 3 - 1;
        int yy = ayr + dy, xx = axr + dx;
        bool ok = ((unsigned)yy < (unsigned)H) && ((unsigned)xx < (unsigned)W);
        int pps = ok ? ((yy << logW) + xx) : 0;
        const char* sAh = (const char*)(arow_h + (size_t)pps * 512 + ci0);
        const char* sAl = (const char*)(arow_l + (size_t)pps * 512 + ci0);
        const char* sBh = (const char*)(brow_h + t * 512 + ci0);
        const char* sBl = (const char*)(brow_l + t * 512 + ci0);
        uint32_t bs = sb + (uint32_t)stg * STAGE_BYTES;
        uint32_t asz = ok ? 16u : 0u;
#pragma unroll
        for (int j = 0; j < 4; ++j) {
            uint32_t sw = SWZ(rawb + j * 16);
            CPA(bs + sw,          sAh + j * 16, asz);
            CPA(bs + 16384u + sw, sAl + j * 16, asz);
            CPA(bs + 32768u + sw, sBh + j * 16, 16u);
            CPA(bs + 49152u + sw, sBl + j * 16, 16u);
        }
        CPA_COMMIT();
    };

    prefetch(0, 0);
    prefetch(1, 1);
    int stg = 0;
    for (int it = 0; it < 72; ++it) {
        if (it < 71) CPA_WAIT1(); else CPA_WAIT0();
        __syncthreads();
        if (it + 2 < 72) {
            int nst = stg + 2; if (nst >= 3) nst -= 3;
            prefetch(it + 2, nst);
        }
        mma_compute64(sb + (uint32_t)stg * STAGE_BYTES, a_rowb, b_rowb, acc);
        if (++stg == 3) stg = 0;
    }
    __syncthreads();

    // epilogue: stage via SMEM (128 x 130 fp32) for coalesced [co][pix] stores
    float* sf = (float*)smem;
#pragma unroll
    for (int i = 0; i < 4; ++i) {
        int row = wm * 64 + i * 16 + (lane >> 2);
#pragma unroll
        for (int jj = 0; jj < 4; ++jj) {
            int col = wn * 32 + jj * 8 + (lane & 3) * 2;
            float* d = acc[i * 4 + jj];
            *(float2*)&sf[row * 130 + col]       = make_float2(d[0], d[1]);
            *(float2*)&sf[(row + 8) * 130 + col] = make_float2(d[2], d[3]);
        }
    }
    __syncthreads();
    {
        int pl = tid & 127, co2 = tid >> 7;
        float* yb = y + (size_t)nimg * 512 * HW + pbase + pl;
#pragma unroll 4
        for (int c = 0; c < 64; ++c) {
            int cl = c * 2 + co2;
            yb[(size_t)(co0 + cl) * HW] = sf[pl * 130 + cl] + bias[co0 + cl];
        }
    }
}

__global__ __launch_bounds__(256, 1) void conv_qkv_mma(
    const float* __restrict__ bq, const float* __restrict__ bk, const float* __restrict__ bv)
{
    int z = blockIdx.z;
    const float* bias = (z == 0) ? bq : (z == 1) ? bk : bv;
    float* y = (z == 0) ? g_y0 : (z == 1) ? g_y1 : g_y2;
    conv_mma_pipe(g_xh + (size_t)z * NELEM, g_xl + (size_t)z * NELEM,
                  g_Bh + (size_t)z * WSZ, g_Bl + (size_t)z * WSZ,
                  bias, y, 32, 8, 3, 8);
}

__global__ __launch_bounds__(256, 1) void conv_o_mma(const float* __restrict__ bo,
                                                     float* __restrict__ out)
{
    conv_mma_pipe(g_sah, g_sal, g_Bh + 3ull * WSZ, g_Bl + 3ull * WSZ,
                  bo, out, 8, 256, 8, 11);
}

// ---------------------------------------------------------------------------
// 3-stage cp.async pipelined GEMM: C(MxN) = A(MxK) * B(NxK)^T, hi/lo bf16
// ---------------------------------------------------------------------------
__device__ __forceinline__ void gemm_mma_pipe(
    const __nv_bfloat16* __restrict__ Ah, const __nv_bfloat16* __restrict__ Al,
    const __nv_bfloat16* __restrict__ Bh, const __nv_bfloat16* __restrict__ Bl,
    int Kdim, int nchunk, float* __restrict__ C, int ldc)
{
    extern __shared__ char smem[];
    uint32_t sb = smem_u32(smem);
    int tid = threadIdx.x, wid = tid >> 5, lane = tid & 31;
    int m0 = blockIdx.y * 128, n0 = blockIdx.x * 128;
    int wm = wid & 1, wn = wid >> 1;

    int ar = tid >> 1, aseg = tid & 1;
    uint32_t rawb = (uint32_t)(ar * 128 + aseg * 64);
    const char* srcA_h = (const char*)(Ah + (size_t)(m0 + ar) * Kdim + aseg * 32);
    const char* srcA_l = (const char*)(Al + (size_t)(m0 + ar) * Kdim + aseg * 32);
    const char* srcB_h = (const char*)(Bh + (size_t)(n0 + ar) * Kdim + aseg * 32);
    const char* srcB_l = (const char*)(Bl + (size_t)(n0 + ar) * Kdim + aseg * 32);

    uint32_t a_rowb = (uint32_t)((wm * 64 + (lane & 15)) * 128) + ((lane & 16) ? 16u : 0u);
    uint32_t b_rowb = (uint32_t)((wn * 32 + (lane & 7) + ((lane & 16) ? 8 : 0)) * 128)
                    + ((lane & 8) ? 16u : 0u);

    float acc[16][4];
#pragma unroll
    for (int i = 0; i < 16; ++i)
#pragma unroll
        for (int j = 0; j < 4; ++j) acc[i][j] = 0.f;

    auto prefetch = [&](int itn, int stg) {
        int cb = itn * 128;                    // byte offset along K (64 bf16)
        uint32_t bs = sb + (uint32_t)stg * STAGE_BYTES;
#pragma unroll
        for (int j = 0; j < 4; ++j) {
            uint32_t sw = SWZ(rawb + j * 16);
            CPA(bs + sw,          srcA_h + cb + j * 16, 16u);
            CPA(bs + 16384u + sw, srcA_l + cb + j * 16, 16u);
            CPA(bs + 32768u + sw, srcB_h + cb + j * 16, 16u);
            CPA(bs + 49152u + sw, srcB_l + cb + j * 16, 16u);
        }
        CPA_COMMIT();
    };

    prefetch(0, 0);
    prefetch(1, 1);
    int stg = 0;
    for (int it = 0; it < nchunk; ++it) {
        if (it < nchunk - 1) CPA_WAIT1(); else CPA_WAIT0();
        __syncthreads();
        if (it + 2 < nchunk) {
            int nst = stg + 2; if (nst >= 3) nst -= 3;
            prefetch(it + 2, nst);
        }
        mma_compute64(sb + (uint32_t)stg * STAGE_BYTES, a_rowb, b_rowb, acc);
        if (++stg == 3) stg = 0;
    }

    // direct epilogue (row-major C)
#pragma unroll
    for (int i = 0; i < 4; ++i) {
        int row = m0 + wm * 64 + i * 16 + (lane >> 2);
#pragma unroll
        for (int jj = 0; jj < 4; ++jj) {
            int col = n0 + wn * 32 + jj * 8 + (lane & 3) * 2;
            float* d = acc[i * 4 + jj];
            *(float2*)&C[(size_t)row * ldc + col]       = make_float2(d[0], d[1]);
            *(float2*)&C[(size_t)(row + 8) * ldc + col] = make_float2(d[2], d[3]);
        }
    }
}

__global__ __launch_bounds__(256, 1) void gemm_scores(float* __restrict__ attn)
{
    int nb = blockIdx.z;
    gemm_mma_pipe(g_Qh + (size_t)nb * 131072, g_Ql + (size_t)nb * 131072,
                  g_Kh + (size_t)nb * 131072, g_Kl + (size_t)nb * 131072,
                  256, 4, attn + (size_t)nb * 262144, 512);
}

__global__ __launch_bounds__(256, 1) void gemm_nnout()
{
    int nb = blockIdx.z;
    gemm_mma_pipe(g_ath + (size_t)nb * 262144, g_atl + (size_t)nb * 262144,
                  g_Vth + (size_t)nb * 131072, g_Vtl + (size_t)nb * 131072,
                  512, 8, g_On + (size_t)nb * 131072, 256);
}

// ---------------------------------------------------------------------------
// gather conv outputs into per-n bf16 hi/lo Q/K (row) and V (transposed)
// ---------------------------------------------------------------------------
__global__ void remap_qkvT()
{
    int t = blockIdx.x * 256 + threadIdx.x;     // 3 * NELEM threads
    int which = t >> 22;
    int e = t & (NELEM - 1);
    if (which == 2) {
        int n = e >> 17, c = (e >> 9) & 255, dk = e & 511;
        int h = c >> 5, r = c & 31;
        float v = g_y2[(h * 4 + (n >> 3)) * 131072 + ((n & 7) * 64 + (dk >> 3)) * 256
                       + (dk & 7) * 32 + r];
        __nv_bfloat16 hh = __float2bfloat16(v);
        g_Vth[e] = hh;
        g_Vtl[e] = __float2bfloat16(v - __bfloat162float(hh));
    } else {
        int n = e >> 17, d = (e >> 8) & 511, h = (e >> 5) & 7, r = e & 31;
        const float* src = which ? g_y1 : g_y0;
        float v = src[(h * 4 + (n >> 3)) * 131072 + ((n & 7) * 64 + (d >> 3)) * 256
                      + (d & 7) * 32 + r];
        __nv_bfloat16 hh = __float2bfloat16(v);
        __nv_bfloat16 ll = __float2bfloat16(v - __bfloat162float(hh));
        if (which) { g_Kh[e] = hh; g_Kl[e] = ll; }
        else       { g_Qh[e] = hh; g_Ql[e] = ll; }
    }
}

// ---------------------------------------------------------------------------
// softmax over 512-wide rows, in place; also emit bf16 hi/lo
// ---------------------------------------------------------------------------
__global__ void softmax_rows(float* __restrict__ attn)
{
    size_t base = (size_t)blockIdx.x * 512;
    float* p = attn + base;
    int tid = threadIdx.x;
    float v0 = p[tid], v1 = p[tid + 256];
    float m = fmaxf(v0, v1);
#pragma unroll
    for (int o = 16; o; o >>= 1) m = fmaxf(m, __shfl_xor_sync(~0u, m, o));
    __shared__ float sm[8], ss[8];
    if ((tid & 31) == 0) sm[tid >> 5] = m;
    __syncthreads();
    if (tid < 8) {
        float mm = sm[tid];
#pragma unroll
        for (int o = 4; o; o >>= 1) mm = fmaxf(mm, __shfl_xor_sync(0xffu, mm, o));
        if (tid == 0) sm[0] = mm;
    }
    __syncthreads();
    float M = sm[0];
    float e0 = expf(v0 - M), e1 = expf(v1 - M);
    float s = e0 + e1;
#pragma unroll
    for (int o = 16; o; o >>= 1) s += __shfl_xor_sync(~0u, s, o);
    if ((tid & 31) == 0) ss[tid >> 5] = s;
    __syncthreads();
    if (tid < 8) {
        float t2 = ss[tid];
#pragma unroll
        for (int o = 4; o; o >>= 1) t2 += __shfl_xor_sync(0xffu, t2, o);
        if (tid == 0) ss[0] = t2;
    }
    __syncthreads();
    float inv = 1.f / ss[0];
    float a0 = e0 * inv, a1 = e1 * inv;
    p[tid] = a0;
    p[tid + 256] = a1;
    __nv_bfloat16 h0 = __float2bfloat16(a0), h1 = __float2bfloat16(a1);
    g_ath[base + tid]       = h0;
    g_atl[base + tid]       = __float2bfloat16(a0 - __bfloat162float(h0));
    g_ath[base + tid + 256] = h1;
    g_atl[base + tid + 256] = __float2bfloat16(a1 - __bfloat162float(h1));
}

// ---------------------------------------------------------------------------
// scatter O into conv_o input, pixel-major bf16 hi/lo [b][p][ci]
// ---------------------------------------------------------------------------
__global__ void remap_sa_bf16()
{
    int e = blockIdx.x * 256 + threadIdx.x;   // NELEM threads; [b][p=s*256+rh][d2]
    int b  = e >> 20;
    int p  = (e >> 9) & 2047;
    int d2 = e & 511;
    int s  = p >> 8;
    int rh = p & 255;
    int r2 = rh >> 3, h2 = rh & 7;
    int n  = b * 8 + s;
    int qd = r2 * 16 + h2 * 2 + (d2 >> 8);
    int rr = (d2 & 255) >> 3;
    int hh = d2 & 7;
    float v = g_On[n * 131072 + qd * 256 + hh * 32 + rr];
    __nv_bfloat16 h = __float2bfloat16(v);
    g_sah[e] = h;
    g_sal[e] = __float2bfloat16(v - __bfloat162float(h));
}

// ---------------------------------------------------------------------------
extern "C" void kernel_launch(void* const* d_in, const int* in_sizes, int n_in,
                              void* d_out, int out_size)
{
    const float* q  = (const float*)d_in[0];
    const float* k  = (const float*)d_in[1];
    const float* v  = (const float*)d_in[2];
    const float* Wq = (const float*)d_in[3];
    const float* bq = (const float*)d_in[4];
    const float* Wk = (const float*)d_in[5];
    const float* bk = (const float*)d_in[6];
    const float* Wv = (const float*)d_in[7];
    const float* bv = (const float*)d_in[8];
    const float* Wo = (const float*)d_in[9];
    const float* bo = (const float*)d_in[10];

    float* y_out    = (float*)d_out;            // (4,512,8,32,8) = 4194304
    float* attn_out = y_out + NELEM;            // (1,32,512,512) = 8388608

    cudaFuncSetAttribute(conv_qkv_mma, cudaFuncAttributeMaxDynamicSharedMemorySize, SMEM_BYTES);
    cudaFuncSetAttribute(conv_o_mma,   cudaFuncAttributeMaxDynamicSharedMemorySize, SMEM_BYTES);
    cudaFuncSetAttribute(gemm_scores,  cudaFuncAttributeMaxDynamicSharedMemorySize, SMEM_BYTES);
    cudaFuncSetAttribute(gemm_nnout,   cudaFuncAttributeMaxDynamicSharedMemorySize, SMEM_BYTES);

    prep_w<<<4 * WSZ / 256, 256>>>(Wq, Wk, Wv, Wo);
    prep_x<<<dim3(8, 16, 96), dim3(32, 8)>>>(q, k, v);
    conv_qkv_mma<<<dim3(64, 4, 3), 256, SMEM_BYTES>>>(bq, bk, bv);
    remap_qkvT<<<3 * NELEM / 256, 256>>>();
    gemm_scores<<<dim3(4, 4, 32), 256, SMEM_BYTES>>>(attn_out);
    softmax_rows<<<32 * 512, 256>>>(attn_out);
    gemm_nnout<<<dim3(2, 4, 32), 256, SMEM_BYTES>>>();
    remap_sa_bf16<<<NELEM / 256, 256>>>();
    conv_o_mma<<<dim3(64, 4, 1), 256, SMEM_BYTES>>>(bo, y_out);
}